// round 4
// baseline (speedup 1.0000x reference)
#include <cuda_runtime.h>

// ---------------------------------------------------------------------------
// WaveConv2d: 4-level db6 DWT -> per-pixel 32x32 channel mix at coarsest level
//             -> 4-level inverse DWT.   All fp32.
//
// Shapes: x (8,32,512,512); w_yl (32,32,42,42); w_yh (32,32,3,42,42)
// Level sizes (both dims): 512 -> 261 -> 136 -> 73 -> 42
// Inverse:                 42 -> 74(crop 73) -> 136 -> 262(crop 261) -> 512
// ---------------------------------------------------------------------------

#define DIV_UP(a,b) (((a)+(b)-1)/(b))
static const int TPB = 256;

__constant__ float c_lo[12] = {
   0.11154074335008017f,  0.4946238903983854f,   0.7511339080215775f,
   0.3152503517092432f,  -0.22626469396516913f, -0.12976686756709563f,
   0.09750160558707936f,  0.02752286553001629f, -0.031582039318031156f,
   0.0005538422009938016f,0.004777257511010651f,-0.00107730108499558f };

// RHI[t] = (-1)^t * H[11-t]
__constant__ float c_hi[12] = {
  -0.00107730108499558f, -0.004777257511010651f, 0.0005538422009938016f,
   0.031582039318031156f, 0.02752286553001629f, -0.09750160558707936f,
  -0.12976686756709563f,  0.22626469396516913f,  0.3152503517092432f,
  -0.7511339080215775f,   0.4946238903983854f,  -0.11154074335008017f };

// ---------------- scratch (static device memory; reused across phases) -----
// sizes in floats
__device__ float g_big[68419584];  // fwd: L1 width lo/hi (2*256*512*261) | inv: L1 col-synth lo/hi
__device__ float g_ll1[17572864];  // fwd: ll1 (256*261*261)              | inv: ll262 (256*262*262)
__device__ float g_mid[18243584];  // fwd: L2 width lo/hi                 | inv: L2 col-synth lo/hi (2*256*262*136)
__device__ float g_ll2[ 4734976];  // fwd: ll2 (256*136*136)              | inv: ll136
__device__ float g_sm [ 5083136];  // fwd: L3 width lo/hi                 | inv: L3 col-synth lo/hi (2*256*136*73)
__device__ float g_ll3[ 1401856];  // fwd: ll3 (256*73*73)                | inv: ll74 (256*74*74)
__device__ float g_tn [ 1591296];  // fwd: L4 width lo/hi                 | inv: L4 col-synth lo/hi (2*256*74*42)
__device__ float g_ll4[  451584];  // ll4 (256*42*42)
__device__ float g_mix[ 1806336];  // mixed yl (451584) + mixed yh4 (3*451584)
__device__ float g_h1 [52316928];  // L1 bands lh,hl,hh (3*256*261*261)
__device__ float g_h2 [14204928];  // L2 bands (3*256*136*136)
__device__ float g_h3 [ 4092672];  // L3 bands (3*256*73*73)
__device__ float g_h4 [ 1354752];  // L4 bands (3*256*42*42)

// ---------------- analysis along width (contiguous dim) --------------------
// in: (nrows, N) dense -> lo,hi: (nrows, nout) dense
__global__ void ana_w(const float* __restrict__ in, float* __restrict__ lo,
                      float* __restrict__ hi, int nrows, int N, int nout, int padL)
{
    int idx = blockIdx.x * blockDim.x + threadIdx.x;
    if (idx >= nrows * nout) return;
    int n = idx % nout;
    int r = idx / nout;
    const float* row = in + (size_t)r * N;
    int base = 2 * n - padL;
    float sl = 0.f, sh = 0.f;
#pragma unroll
    for (int t = 0; t < 12; ++t) {
        int s = base + t;
        if (s < 0)   s = -1 - s;           // symmetric reflect (single bounce: pad<=11<N)
        if (s >= N)  s = 2 * N - 1 - s;
        float v = __ldg(row + s);
        sl = fmaf(v, c_lo[t], sl);
        sh = fmaf(v, c_hi[t], sh);
    }
    size_t o = (size_t)r * nout + n;
    lo[o] = sl;
    hi[o] = sh;
}

// ---------------- analysis along height ------------------------------------
// in: (nimg, Hin, W) dense -> lo,hi: (nimg, nout, W) dense
__global__ void ana_h(const float* __restrict__ in, float* __restrict__ lo,
                      float* __restrict__ hi, int nimg, int Hin, int W,
                      int nout, int padL)
{
    int idx = blockIdx.x * blockDim.x + threadIdx.x;
    int total = nimg * nout * W;
    if (idx >= total) return;
    int w   = idx % W;
    int r   = (idx / W) % nout;
    int img = idx / (W * nout);
    const float* base = in + (size_t)img * Hin * W + w;
    int b0 = 2 * r - padL;
    float sl = 0.f, sh = 0.f;
#pragma unroll
    for (int t = 0; t < 12; ++t) {
        int s = b0 + t;
        if (s < 0)    s = -1 - s;
        if (s >= Hin) s = 2 * Hin - 1 - s;
        float v = __ldg(base + (size_t)s * W);
        sl = fmaf(v, c_lo[t], sl);
        sh = fmaf(v, c_hi[t], sh);
    }
    size_t o = ((size_t)img * nout + r) * W + w;
    lo[o] = sl;
    hi[o] = sh;
}

// ---------------- synthesis along height -----------------------------------
// a (lowpass src), b (highpass src), each pitched; only first Nin rows / W cols used.
// out: (nimg, On=2*Nin-10, W) dense.
__global__ void syn_h(const float* __restrict__ a, size_t a_is, int a_pitch,
                      const float* __restrict__ b, size_t b_is, int b_pitch,
                      float* __restrict__ out, int nimg, int Nin, int W, int On)
{
    int idx = blockIdx.x * blockDim.x + threadIdx.x;
    int total = nimg * On * W;
    if (idx >= total) return;
    int w   = idx % W;
    int r   = (idx / W) % On;
    int img = idx / (W * On);
    const float* pa = a + (size_t)img * a_is + w;
    const float* pb = b + (size_t)img * b_is + w;
    int j0 = r >> 1;               // j in [n/2, n/2+5] is always within [0, Nin-1]
    float s = 0.f;
#pragma unroll
    for (int k = 0; k < 6; ++k) {
        int j  = j0 + k;
        int ci = r - 2 * j + 10;   // in [0,11]
        s = fmaf(__ldg(pa + (size_t)j * a_pitch), c_lo[ci], s);
        s = fmaf(__ldg(pb + (size_t)j * b_pitch), c_hi[ci], s);
    }
    out[((size_t)img * On + r) * W + w] = s;
}

// ---------------- synthesis along width ------------------------------------
// a,b: (nrows, N) dense -> out: (nrows, On=2N-10) dense
__global__ void syn_w(const float* __restrict__ a, const float* __restrict__ b,
                      float* __restrict__ out, int nrows, int N, int On)
{
    int idx = blockIdx.x * blockDim.x + threadIdx.x;
    if (idx >= nrows * On) return;
    int n = idx % On;
    int r = idx / On;
    const float* pa = a + (size_t)r * N;
    const float* pb = b + (size_t)r * N;
    int j0 = n >> 1;
    float s = 0.f;
#pragma unroll
    for (int k = 0; k < 6; ++k) {
        int j  = j0 + k;
        int ci = n - 2 * j + 10;
        s = fmaf(__ldg(pa + j), c_lo[ci], s);
        s = fmaf(__ldg(pb + j), c_hi[ci], s);
    }
    out[(size_t)r * On + n] = s;
}

// ---------------- channel mixing at coarsest level --------------------------
// yl: in (256=8b*32i, 1764), w (32i,32o,1764), out (8b*32o, 1764)
__global__ void mix_yl(const float* __restrict__ in, const float* __restrict__ w,
                       float* __restrict__ out)
{
    int idx = blockIdx.x * blockDim.x + threadIdx.x;
    const int P = 1764;
    if (idx >= 8 * 32 * P) return;
    int p = idx % P;
    int o = (idx / P) % 32;
    int b = idx / (P * 32);
    float s = 0.f;
#pragma unroll 4
    for (int i = 0; i < 32; ++i)
        s = fmaf(__ldg(in + (size_t)(b * 32 + i) * P + p),
                 __ldg(w + (size_t)(i * 32 + o) * P + p), s);
    out[(size_t)(b * 32 + o) * P + p] = s;
}

// yh: in (3c, 256, 1764), w (32i,32o,3c,1764), out (3c, 256, 1764)
__global__ void mix_yh(const float* __restrict__ in, const float* __restrict__ w,
                       float* __restrict__ out)
{
    int idx = blockIdx.x * blockDim.x + threadIdx.x;
    const int P = 1764;
    if (idx >= 3 * 8 * 32 * P) return;
    int p = idx % P;
    int o = (idx / P) % 32;
    int b = (idx / (P * 32)) % 8;
    int c = idx / (P * 32 * 8);
    float s = 0.f;
#pragma unroll 4
    for (int i = 0; i < 32; ++i)
        s = fmaf(__ldg(in + (size_t)c * 256 * P + (size_t)(b * 32 + i) * P + p),
                 __ldg(w + ((size_t)(i * 32 + o) * 3 + c) * P + p), s);
    out[(size_t)c * 256 * P + (size_t)(b * 32 + o) * P + p] = s;
}

// ---------------------------------------------------------------------------
extern "C" void kernel_launch(void* const* d_in, const int* in_sizes, int n_in,
                              void* d_out, int out_size)
{
    (void)in_sizes; (void)n_in; (void)out_size;
    const float* x   = (const float*)d_in[0];
    const float* wyl = (const float*)d_in[1];
    const float* wyh = (const float*)d_in[2];
    float* out = (float*)d_out;

    float *big, *ll1, *mid, *ll2, *sm, *ll3, *tn, *ll4, *mix, *h1, *h2, *h3, *h4;
    cudaGetSymbolAddress((void**)&big, g_big);
    cudaGetSymbolAddress((void**)&ll1, g_ll1);
    cudaGetSymbolAddress((void**)&mid, g_mid);
    cudaGetSymbolAddress((void**)&ll2, g_ll2);
    cudaGetSymbolAddress((void**)&sm,  g_sm);
    cudaGetSymbolAddress((void**)&ll3, g_ll3);
    cudaGetSymbolAddress((void**)&tn,  g_tn);
    cudaGetSymbolAddress((void**)&ll4, g_ll4);
    cudaGetSymbolAddress((void**)&mix, g_mix);
    cudaGetSymbolAddress((void**)&h1,  g_h1);
    cudaGetSymbolAddress((void**)&h2,  g_h2);
    cudaGetSymbolAddress((void**)&h3,  g_h3);
    cudaGetSymbolAddress((void**)&h4,  g_h4);

    const int B = 256;                  // images = batch * channels
    const size_t bs1 = 17438976;        // 256*261*261
    const size_t bs2 =  4734976;        // 256*136*136
    const size_t bs3 =  1364224;        // 256*73*73
    const size_t bs4 =   451584;        // 256*42*42

    // ---------------- forward DWT ----------------
    // L1: 512 -> 261
    {
        int nr = B * 512, N = 512, o = 261;
        size_t half = (size_t)nr * o;                       // 34,209,792
        ana_w<<<DIV_UP(nr * o, TPB), TPB>>>(x, big, big + half, nr, N, o, 10);
        int tot = B * 261 * 261;
        ana_h<<<DIV_UP(tot, TPB), TPB>>>(big,        ll1,       h1,            B, 512, 261, 261, 10); // ll1, lh
        ana_h<<<DIV_UP(tot, TPB), TPB>>>(big + half, h1 + bs1,  h1 + 2 * bs1,  B, 512, 261, 261, 10); // hl, hh
    }
    // L2: 261 -> 136
    {
        int nr = B * 261, N = 261, o = 136;
        size_t half = (size_t)nr * o;                       // 9,086,976
        ana_w<<<DIV_UP(nr * o, TPB), TPB>>>(ll1, mid, mid + half, nr, N, o, 10);
        int tot = B * 136 * 136;
        ana_h<<<DIV_UP(tot, TPB), TPB>>>(mid,        ll2,       h2,            B, 261, 136, 136, 10);
        ana_h<<<DIV_UP(tot, TPB), TPB>>>(mid + half, h2 + bs2,  h2 + 2 * bs2,  B, 261, 136, 136, 10);
    }
    // L3: 136 -> 73
    {
        int nr = B * 136, N = 136, o = 73;
        size_t half = (size_t)nr * o;                       // 2,541,568
        ana_w<<<DIV_UP(nr * o, TPB), TPB>>>(ll2, sm, sm + half, nr, N, o, 10);
        int tot = B * 73 * 73;
        ana_h<<<DIV_UP(tot, TPB), TPB>>>(sm,        ll3,       h3,            B, 136, 73, 73, 10);
        ana_h<<<DIV_UP(tot, TPB), TPB>>>(sm + half, h3 + bs3,  h3 + 2 * bs3,  B, 136, 73, 73, 10);
    }
    // L4: 73 -> 42
    {
        int nr = B * 73, N = 73, o = 42;
        size_t half = (size_t)nr * o;                       // 784,896
        ana_w<<<DIV_UP(nr * o, TPB), TPB>>>(ll3, tn, tn + half, nr, N, o, 10);
        int tot = B * 42 * 42;
        ana_h<<<DIV_UP(tot, TPB), TPB>>>(tn,        ll4,       h4,            B, 73, 42, 42, 10);
        ana_h<<<DIV_UP(tot, TPB), TPB>>>(tn + half, h4 + bs4,  h4 + 2 * bs4,  B, 73, 42, 42, 10);
    }

    // ---------------- channel mix ----------------
    mix_yl<<<DIV_UP(8 * 32 * 1764, TPB), TPB>>>(ll4, wyl, mix);
    mix_yh<<<DIV_UP(3 * 8 * 32 * 1764, TPB), TPB>>>(h4, wyh, mix + bs4);

    // ---------------- inverse DWT ----------------
    const float* myl = mix;             // mixed yl   (256,42,42)
    const float* mh  = mix + bs4;       // mixed yh4  (3,256,42,42)

    // L4 inverse: 42 -> 74 (store ll74 in g_ll3, pitch 74)
    {
        size_t half = (size_t)B * 74 * 42;                  // 795,648
        int tot = B * 74 * 42;
        syn_h<<<DIV_UP(tot, TPB), TPB>>>(myl,       1764, 42, mh,           1764, 42, tn,        B, 42, 42, 74); // lo
        syn_h<<<DIV_UP(tot, TPB), TPB>>>(mh + bs4,  1764, 42, mh + 2 * bs4, 1764, 42, tn + half, B, 42, 42, 74); // hi
        syn_w<<<DIV_UP(B * 74 * 74, TPB), TPB>>>(tn, tn + half, ll3, B * 74, 42, 74);
    }
    // L3 inverse: crop ll74 -> 73; 73 -> 136 (store ll136 in g_ll2)
    {
        size_t half = (size_t)B * 136 * 73;                 // 2,541,568
        int tot = B * 136 * 73;
        syn_h<<<DIV_UP(tot, TPB), TPB>>>(ll3,      5476, 74, h3,           5329, 73, sm,        B, 73, 73, 136);
        syn_h<<<DIV_UP(tot, TPB), TPB>>>(h3 + bs3, 5329, 73, h3 + 2 * bs3, 5329, 73, sm + half, B, 73, 73, 136);
        syn_w<<<DIV_UP(B * 136 * 136, TPB), TPB>>>(sm, sm + half, ll2, B * 136, 73, 136);
    }
    // L2 inverse: 136 -> 262 (store ll262 in g_ll1, pitch 262)
    {
        size_t half = (size_t)B * 262 * 136;                // 9,121,792
        int tot = B * 262 * 136;
        syn_h<<<DIV_UP(tot, TPB), TPB>>>(ll2,      18496, 136, h2,           18496, 136, mid,        B, 136, 136, 262);
        syn_h<<<DIV_UP(tot, TPB), TPB>>>(h2 + bs2, 18496, 136, h2 + 2 * bs2, 18496, 136, mid + half, B, 136, 136, 262);
        syn_w<<<DIV_UP(B * 262 * 262, TPB), TPB>>>(mid, mid + half, ll1, B * 262, 136, 262);
    }
    // L1 inverse: crop ll262 -> 261; 261 -> 512 -> d_out
    {
        size_t half = (size_t)B * 512 * 261;                // 34,209,792
        int tot = B * 512 * 261;
        syn_h<<<DIV_UP(tot, TPB), TPB>>>(ll1,      68644, 262, h1,           68121, 261, big,        B, 261, 261, 512);
        syn_h<<<DIV_UP(tot, TPB), TPB>>>(h1 + bs1, 68121, 261, h1 + 2 * bs1, 68121, 261, big + half, B, 261, 261, 512);
        syn_w<<<DIV_UP(B * 512 * 512, TPB), TPB>>>(big, big + half, out, B * 512, 261, 512);
    }
}

// round 5
// speedup vs baseline: 2.1129x; 2.1129x over previous
#include <cuda_runtime.h>

// ---------------------------------------------------------------------------
// WaveConv2d: 4-level db6 DWT -> per-pixel 32x32 channel mix at coarsest level
//             -> 4-level inverse DWT.   All fp32.
//
// R4: multi-output-per-thread register sliding windows.
//   analysis: 4 outputs/thread from an 18-wide window, interior fast path
//   synthesis: even/odd output pair shares identical 6 lo + 6 hi inputs
// ---------------------------------------------------------------------------

#define DIV_UP(a,b) (((a)+(b)-1)/(b))
static const int TPB = 256;

__constant__ float c_lo[12] = {
   0.11154074335008017f,  0.4946238903983854f,   0.7511339080215775f,
   0.3152503517092432f,  -0.22626469396516913f, -0.12976686756709563f,
   0.09750160558707936f,  0.02752286553001629f, -0.031582039318031156f,
   0.0005538422009938016f,0.004777257511010651f,-0.00107730108499558f };

// RHI[t] = (-1)^t * H[11-t]
__constant__ float c_hi[12] = {
  -0.00107730108499558f, -0.004777257511010651f, 0.0005538422009938016f,
   0.031582039318031156f, 0.02752286553001629f, -0.09750160558707936f,
  -0.12976686756709563f,  0.22626469396516913f,  0.3152503517092432f,
  -0.7511339080215775f,   0.4946238903983854f,  -0.11154074335008017f };

// ---------------- scratch (static device memory; reused across phases) -----
__device__ float g_big[68419584];  // fwd: L1 width lo/hi | inv: L1 col-synth lo/hi
__device__ float g_ll1[17572864];  // fwd: ll1            | inv: ll262 (256*262*262)
__device__ float g_mid[18243584];  // fwd: L2 width lo/hi | inv: L2 col-synth lo/hi
__device__ float g_ll2[ 4734976];  // fwd: ll2            | inv: ll136
__device__ float g_sm [ 5083136];  // fwd: L3 width lo/hi | inv: L3 col-synth lo/hi
__device__ float g_ll3[ 1401856];  // fwd: ll3            | inv: ll74 (256*74*74)
__device__ float g_tn [ 1591296];  // fwd: L4 width lo/hi | inv: L4 col-synth lo/hi
__device__ float g_ll4[  451584];  // ll4 (256*42*42)
__device__ float g_mix[ 1806336];  // mixed yl + mixed yh4
__device__ float g_h1 [52316928];  // L1 bands lh,hl,hh
__device__ float g_h2 [14204928];  // L2 bands
__device__ float g_h3 [ 4092672];  // L3 bands
__device__ float g_h4 [ 1354752];  // L4 bands

// ---------------- analysis along width: 4 outputs / thread ------------------
// in: (nrows, N) dense -> lo,hi: (nrows, nout) dense
__global__ void ana_w(const float* __restrict__ in, float* __restrict__ lo,
                      float* __restrict__ hi, int nrows, int N, int nout, int gpr)
{
    int idx = blockIdx.x * blockDim.x + threadIdx.x;
    if (idx >= nrows * gpr) return;
    int g = idx % gpr;
    int r = idx / gpr;
    int n0 = g * 4;
    const float* row = in + (size_t)r * N;
    int base = 2 * n0 - 10;

    float w[18];
    if (base >= 0 && base + 17 < N) {
#pragma unroll
        for (int t = 0; t < 18; ++t) w[t] = __ldg(row + base + t);
    } else {
#pragma unroll
        for (int t = 0; t < 18; ++t) {
            int s = base + t;
            if (s < 0)   s = -1 - s;          // single reflect is sufficient
            if (s >= N)  s = 2 * N - 1 - s;
            w[t] = __ldg(row + s);
        }
    }

    size_t o = (size_t)r * nout + n0;
#pragma unroll
    for (int k = 0; k < 4; ++k) {
        if (n0 + k < nout) {
            float sl = 0.f, sh = 0.f;
#pragma unroll
            for (int t = 0; t < 12; ++t) {
                float v = w[2 * k + t];
                sl = fmaf(v, c_lo[t], sl);
                sh = fmaf(v, c_hi[t], sh);
            }
            lo[o + k] = sl;
            hi[o + k] = sh;
        }
    }
}

// ---------------- analysis along height: 4 output rows / thread -------------
// in: (nimg, Hin, W) dense -> lo,hi: (nimg, nout, W) dense
__global__ void ana_h(const float* __restrict__ in, float* __restrict__ lo,
                      float* __restrict__ hi, int nimg, int Hin, int W,
                      int nout, int gph)
{
    int idx = blockIdx.x * blockDim.x + threadIdx.x;
    int total = nimg * gph * W;
    if (idx >= total) return;
    int w_  = idx % W;
    int g   = (idx / W) % gph;
    int img = idx / (W * gph);
    int r0  = g * 4;
    const float* basep = in + (size_t)img * Hin * W + w_;
    int b0 = 2 * r0 - 10;

    float win[18];
    if (b0 >= 0 && b0 + 17 < Hin) {
#pragma unroll
        for (int t = 0; t < 18; ++t)
            win[t] = __ldg(basep + (size_t)(b0 + t) * W);
    } else {
#pragma unroll
        for (int t = 0; t < 18; ++t) {
            int s = b0 + t;
            if (s < 0)    s = -1 - s;
            if (s >= Hin) s = 2 * Hin - 1 - s;
            win[t] = __ldg(basep + (size_t)s * W);
        }
    }

#pragma unroll
    for (int k = 0; k < 4; ++k) {
        if (r0 + k < nout) {
            float sl = 0.f, sh = 0.f;
#pragma unroll
            for (int t = 0; t < 12; ++t) {
                float v = win[2 * k + t];
                sl = fmaf(v, c_lo[t], sl);
                sh = fmaf(v, c_hi[t], sh);
            }
            size_t o = ((size_t)img * nout + r0 + k) * W + w_;
            lo[o] = sl;
            hi[o] = sh;
        }
    }
}

// ---------------- synthesis along height: output-row pair / thread ----------
// rows 2m and 2m+1 both consume exactly rows j=m..m+5 of a and b.
// a,b pitched; out: (nimg, On, W) dense, On even.
__global__ void syn_h(const float* __restrict__ a, size_t a_is, int a_pitch,
                      const float* __restrict__ b, size_t b_is, int b_pitch,
                      float* __restrict__ out, int nimg, int W, int On)
{
    int idx = blockIdx.x * blockDim.x + threadIdx.x;
    int half = On >> 1;
    int total = nimg * half * W;
    if (idx >= total) return;
    int w_  = idx % W;
    int m   = (idx / W) % half;
    int img = idx / (W * half);
    const float* pa = a + (size_t)img * a_is + (size_t)m * a_pitch + w_;
    const float* pb = b + (size_t)img * b_is + (size_t)m * b_pitch + w_;
    float se = 0.f, so = 0.f;           // even row 2m, odd row 2m+1
#pragma unroll
    for (int k = 0; k < 6; ++k) {
        float va = __ldg(pa + (size_t)k * a_pitch);
        float vb = __ldg(pb + (size_t)k * b_pitch);
        se = fmaf(va, c_lo[10 - 2 * k], se);
        se = fmaf(vb, c_hi[10 - 2 * k], se);
        so = fmaf(va, c_lo[11 - 2 * k], so);
        so = fmaf(vb, c_hi[11 - 2 * k], so);
    }
    float* po = out + ((size_t)img * On + 2 * m) * W + w_;
    po[0] = se;
    po[W] = so;
}

// ---------------- synthesis along width: output pair / thread ----------------
// a,b: (nrows, N) dense -> out: (nrows, On) dense, On even; float2 store.
__global__ void syn_w(const float* __restrict__ a, const float* __restrict__ b,
                      float* __restrict__ out, int nrows, int N, int On)
{
    int idx = blockIdx.x * blockDim.x + threadIdx.x;
    int half = On >> 1;
    if (idx >= nrows * half) return;
    int m = idx % half;
    int r = idx / half;
    const float* pa = a + (size_t)r * N + m;
    const float* pb = b + (size_t)r * N + m;
    float se = 0.f, so = 0.f;
#pragma unroll
    for (int k = 0; k < 6; ++k) {
        float va = __ldg(pa + k);
        float vb = __ldg(pb + k);
        se = fmaf(va, c_lo[10 - 2 * k], se);
        se = fmaf(vb, c_hi[10 - 2 * k], se);
        so = fmaf(va, c_lo[11 - 2 * k], so);
        so = fmaf(vb, c_hi[11 - 2 * k], so);
    }
    float2 v2 = make_float2(se, so);
    *reinterpret_cast<float2*>(out + (size_t)r * On + 2 * m) = v2;
}

// ---------------- channel mixing at coarsest level --------------------------
__global__ void mix_yl(const float* __restrict__ in, const float* __restrict__ w,
                       float* __restrict__ out)
{
    int idx = blockIdx.x * blockDim.x + threadIdx.x;
    const int P = 1764;
    if (idx >= 8 * 32 * P) return;
    int p = idx % P;
    int o = (idx / P) % 32;
    int b = idx / (P * 32);
    float s = 0.f;
#pragma unroll 8
    for (int i = 0; i < 32; ++i)
        s = fmaf(__ldg(in + (size_t)(b * 32 + i) * P + p),
                 __ldg(w + (size_t)(i * 32 + o) * P + p), s);
    out[(size_t)(b * 32 + o) * P + p] = s;
}

__global__ void mix_yh(const float* __restrict__ in, const float* __restrict__ w,
                       float* __restrict__ out)
{
    int idx = blockIdx.x * blockDim.x + threadIdx.x;
    const int P = 1764;
    if (idx >= 3 * 8 * 32 * P) return;
    int p = idx % P;
    int o = (idx / P) % 32;
    int b = (idx / (P * 32)) % 8;
    int c = idx / (P * 32 * 8);
    float s = 0.f;
#pragma unroll 8
    for (int i = 0; i < 32; ++i)
        s = fmaf(__ldg(in + (size_t)c * 256 * P + (size_t)(b * 32 + i) * P + p),
                 __ldg(w + ((size_t)(i * 32 + o) * 3 + c) * P + p), s);
    out[(size_t)c * 256 * P + (size_t)(b * 32 + o) * P + p] = s;
}

// ---------------------------------------------------------------------------
extern "C" void kernel_launch(void* const* d_in, const int* in_sizes, int n_in,
                              void* d_out, int out_size)
{
    (void)in_sizes; (void)n_in; (void)out_size;
    const float* x   = (const float*)d_in[0];
    const float* wyl = (const float*)d_in[1];
    const float* wyh = (const float*)d_in[2];
    float* out = (float*)d_out;

    float *big, *ll1, *mid, *ll2, *sm, *ll3, *tn, *ll4, *mix, *h1, *h2, *h3, *h4;
    cudaGetSymbolAddress((void**)&big, g_big);
    cudaGetSymbolAddress((void**)&ll1, g_ll1);
    cudaGetSymbolAddress((void**)&mid, g_mid);
    cudaGetSymbolAddress((void**)&ll2, g_ll2);
    cudaGetSymbolAddress((void**)&sm,  g_sm);
    cudaGetSymbolAddress((void**)&ll3, g_ll3);
    cudaGetSymbolAddress((void**)&tn,  g_tn);
    cudaGetSymbolAddress((void**)&ll4, g_ll4);
    cudaGetSymbolAddress((void**)&mix, g_mix);
    cudaGetSymbolAddress((void**)&h1,  g_h1);
    cudaGetSymbolAddress((void**)&h2,  g_h2);
    cudaGetSymbolAddress((void**)&h3,  g_h3);
    cudaGetSymbolAddress((void**)&h4,  g_h4);

    const int B = 256;                  // images = batch * channels
    const size_t bs1 = 17438976;        // 256*261*261
    const size_t bs2 =  4734976;        // 256*136*136
    const size_t bs3 =  1364224;        // 256*73*73
    const size_t bs4 =   451584;        // 256*42*42

    // ---------------- forward DWT ----------------
    // L1: 512 -> 261
    {
        int nr = B * 512, N = 512, o = 261, gpr = DIV_UP(o, 4);
        size_t half = (size_t)nr * o;
        ana_w<<<DIV_UP(nr * gpr, TPB), TPB>>>(x, big, big + half, nr, N, o, gpr);
        int gph = DIV_UP(261, 4);
        int tot = B * gph * 261;
        ana_h<<<DIV_UP(tot, TPB), TPB>>>(big,        ll1,      h1,           B, 512, 261, 261, gph);
        ana_h<<<DIV_UP(tot, TPB), TPB>>>(big + half, h1 + bs1, h1 + 2 * bs1, B, 512, 261, 261, gph);
    }
    // L2: 261 -> 136
    {
        int nr = B * 261, N = 261, o = 136, gpr = DIV_UP(o, 4);
        size_t half = (size_t)nr * o;
        ana_w<<<DIV_UP(nr * gpr, TPB), TPB>>>(ll1, mid, mid + half, nr, N, o, gpr);
        int gph = DIV_UP(136, 4);
        int tot = B * gph * 136;
        ana_h<<<DIV_UP(tot, TPB), TPB>>>(mid,        ll2,      h2,           B, 261, 136, 136, gph);
        ana_h<<<DIV_UP(tot, TPB), TPB>>>(mid + half, h2 + bs2, h2 + 2 * bs2, B, 261, 136, 136, gph);
    }
    // L3: 136 -> 73
    {
        int nr = B * 136, N = 136, o = 73, gpr = DIV_UP(o, 4);
        size_t half = (size_t)nr * o;
        ana_w<<<DIV_UP(nr * gpr, TPB), TPB>>>(ll2, sm, sm + half, nr, N, o, gpr);
        int gph = DIV_UP(73, 4);
        int tot = B * gph * 73;
        ana_h<<<DIV_UP(tot, TPB), TPB>>>(sm,        ll3,      h3,           B, 136, 73, 73, gph);
        ana_h<<<DIV_UP(tot, TPB), TPB>>>(sm + half, h3 + bs3, h3 + 2 * bs3, B, 136, 73, 73, gph);
    }
    // L4: 73 -> 42
    {
        int nr = B * 73, N = 73, o = 42, gpr = DIV_UP(o, 4);
        size_t half = (size_t)nr * o;
        ana_w<<<DIV_UP(nr * gpr, TPB), TPB>>>(ll3, tn, tn + half, nr, N, o, gpr);
        int gph = DIV_UP(42, 4);
        int tot = B * gph * 42;
        ana_h<<<DIV_UP(tot, TPB), TPB>>>(tn,        ll4,      h4,           B, 73, 42, 42, gph);
        ana_h<<<DIV_UP(tot, TPB), TPB>>>(tn + half, h4 + bs4, h4 + 2 * bs4, B, 73, 42, 42, gph);
    }

    // ---------------- channel mix ----------------
    mix_yl<<<DIV_UP(8 * 32 * 1764, TPB), TPB>>>(ll4, wyl, mix);
    mix_yh<<<DIV_UP(3 * 8 * 32 * 1764, TPB), TPB>>>(h4, wyh, mix + bs4);

    // ---------------- inverse DWT ----------------
    const float* myl = mix;             // mixed yl   (256,42,42)
    const float* mh  = mix + bs4;       // mixed yh4  (3,256,42,42)

    // L4 inverse: 42 -> 74 (ll74 stored in g_ll3, pitch 74)
    {
        size_t half = (size_t)B * 74 * 42;
        int tot = B * (74 / 2) * 42;
        syn_h<<<DIV_UP(tot, TPB), TPB>>>(myl,      1764, 42, mh,           1764, 42, tn,        B, 42, 74);
        syn_h<<<DIV_UP(tot, TPB), TPB>>>(mh + bs4, 1764, 42, mh + 2 * bs4, 1764, 42, tn + half, B, 42, 74);
        syn_w<<<DIV_UP(B * 74 * (74 / 2), TPB), TPB>>>(tn, tn + half, ll3, B * 74, 42, 74);
    }
    // L3 inverse: crop ll74 -> 73; 73 -> 136
    {
        size_t half = (size_t)B * 136 * 73;
        int tot = B * (136 / 2) * 73;
        syn_h<<<DIV_UP(tot, TPB), TPB>>>(ll3,      5476, 74, h3,           5329, 73, sm,        B, 73, 136);
        syn_h<<<DIV_UP(tot, TPB), TPB>>>(h3 + bs3, 5329, 73, h3 + 2 * bs3, 5329, 73, sm + half, B, 73, 136);
        syn_w<<<DIV_UP(B * 136 * (136 / 2), TPB), TPB>>>(sm, sm + half, ll2, B * 136, 73, 136);
    }
    // L2 inverse: 136 -> 262 (ll262 stored in g_ll1, pitch 262)
    {
        size_t half = (size_t)B * 262 * 136;
        int tot = B * (262 / 2) * 136;
        syn_h<<<DIV_UP(tot, TPB), TPB>>>(ll2,      18496, 136, h2,           18496, 136, mid,        B, 136, 262);
        syn_h<<<DIV_UP(tot, TPB), TPB>>>(h2 + bs2, 18496, 136, h2 + 2 * bs2, 18496, 136, mid + half, B, 136, 262);
        syn_w<<<DIV_UP(B * 262 * (262 / 2), TPB), TPB>>>(mid, mid + half, ll1, B * 262, 136, 262);
    }
    // L1 inverse: crop ll262 -> 261; 261 -> 512 -> d_out
    {
        size_t half = (size_t)B * 512 * 261;
        int tot = B * (512 / 2) * 261;
        syn_h<<<DIV_UP(tot, TPB), TPB>>>(ll1,      68644, 262, h1,           68121, 261, big,        B, 261, 512);
        syn_h<<<DIV_UP(tot, TPB), TPB>>>(h1 + bs1, 68121, 261, h1 + 2 * bs1, 68121, 261, big + half, B, 261, 512);
        syn_w<<<DIV_UP(B * 512 * (512 / 2), TPB), TPB>>>(big, big + half, out, B * 512, 261, 512);
    }
}

// round 6
// speedup vs baseline: 2.2925x; 1.0850x over previous
#include <cuda_runtime.h>

// ---------------------------------------------------------------------------
// WaveConv2d: 4-level db6 DWT -> per-pixel 32x32 channel mix at coarsest level
//             -> 4-level inverse DWT.  All fp32.
//
// R5: per-level 2D fusion in shared memory.
//   forward: one kernel/level: 74x74 smem input tile -> width pass -> height
//            pass -> 4 bands (32x32 outputs/block)
//   inverse: one kernel/level: 4x 37x37 smem band tiles -> height synth ->
//            width synth -> 64x64 output tile
//   coefficients constexpr -> FFMA-immediate (rt_SMSP=1)
// ---------------------------------------------------------------------------

#define DIV_UP(a,b) (((a)+(b)-1)/(b))

__device__ constexpr float c_lo[12] = {
   0.11154074335008017f,  0.4946238903983854f,   0.7511339080215775f,
   0.3152503517092432f,  -0.22626469396516913f, -0.12976686756709563f,
   0.09750160558707936f,  0.02752286553001629f, -0.031582039318031156f,
   0.0005538422009938016f,0.004777257511010651f,-0.00107730108499558f };

// RHI[t] = (-1)^t * H[11-t]
__device__ constexpr float c_hi[12] = {
  -0.00107730108499558f, -0.004777257511010651f, 0.0005538422009938016f,
   0.031582039318031156f, 0.02752286553001629f, -0.09750160558707936f,
  -0.12976686756709563f,  0.22626469396516913f,  0.3152503517092432f,
  -0.7511339080215775f,   0.4946238903983854f,  -0.11154074335008017f };

// ---------------- scratch (static device memory; reused across phases) -----
__device__ float g_ll1[17572864];  // fwd: ll1 (256*261*261) | inv: ll262 (256*262*262)
__device__ float g_ll2[ 4734976];  // fwd: ll2 (256*136*136) | inv: ll136
__device__ float g_ll3[ 1401856];  // fwd: ll3 (256*73*73)   | inv: ll74 (256*74*74)
__device__ float g_ll4[  451584];  // ll4 (256*42*42)
__device__ float g_mix[ 1806336];  // mixed yl + mixed yh4
__device__ float g_h1 [52316928];  // L1 bands lh,hl,hh (3*256*261*261)
__device__ float g_h2 [14204928];  // L2 bands
__device__ float g_h3 [ 4092672];  // L3 bands
__device__ float g_h4 [ 1354752];  // L4 bands

// ================= fused forward level ======================================
// in: (B, N, N) dense.  out: ll/lh/hl/hh, each (B, o, o) dense (img stride o*o)
#define OT  32          // output tile (both dims)
#define IT  74          // input tile span = 2*OT+10
#define ITP 75
#define LHP 33

__global__ __launch_bounds__(256) void fdwt2(
    const float* __restrict__ in, int N,
    float* __restrict__ ll, float* __restrict__ lh,
    float* __restrict__ hl, float* __restrict__ hh,
    int o, int tilesX)
{
    __shared__ float s_in[IT * ITP];
    __shared__ float s_lo[IT * LHP];
    __shared__ float s_hi[IT * LHP];

    int img = blockIdx.y;
    int ty = blockIdx.x / tilesX, tx = blockIdx.x % tilesX;
    int r0 = ty * OT, c0 = tx * OT;
    int tid = threadIdx.x;
    const float* ip = in + (size_t)img * N * N;
    int rbase = 2 * r0 - 10, cbase = 2 * c0 - 10;

    // stage A: load input tile (reflect at borders; single bounce suffices)
    if (rbase >= 0 && rbase + IT <= N && cbase >= 0 && cbase + IT <= N) {
        for (int t = tid; t < IT * IT; t += 256) {
            int j = t % IT, i = t / IT;
            s_in[i * ITP + j] = __ldg(ip + (size_t)(rbase + i) * N + cbase + j);
        }
    } else {
        for (int t = tid; t < IT * IT; t += 256) {
            int j = t % IT, i = t / IT;
            int s = rbase + i; if (s < 0) s = -1 - s; if (s >= N) s = 2 * N - 1 - s;
            int u = cbase + j; if (u < 0) u = -1 - u; if (u >= N) u = 2 * N - 1 - u;
            s_in[i * ITP + j] = __ldg(ip + (size_t)s * N + u);
        }
    }
    __syncthreads();

    // stage B: width analysis (IT rows x OT cols)
    for (int t = tid; t < IT * OT; t += 256) {
        int c = t % OT, i = t / OT;
        const float* p = &s_in[i * ITP + 2 * c];
        float sl = 0.f, sh = 0.f;
#pragma unroll
        for (int k = 0; k < 12; ++k) {
            float v = p[k];
            sl = fmaf(v, c_lo[k], sl);
            sh = fmaf(v, c_hi[k], sh);
        }
        s_lo[i * LHP + c] = sl;
        s_hi[i * LHP + c] = sh;
    }
    __syncthreads();

    // stage C: height analysis (OT x OT), write 4 bands
    for (int t = tid; t < OT * OT; t += 256) {
        int c = t % OT, r = t / OT;
        int gr = r0 + r, gc = c0 + c;
        if (gr < o && gc < o) {
            float a = 0.f, b = 0.f, cc = 0.f, d = 0.f;
#pragma unroll
            for (int k = 0; k < 12; ++k) {
                float vl = s_lo[(2 * r + k) * LHP + c];
                float vh = s_hi[(2 * r + k) * LHP + c];
                a  = fmaf(vl, c_lo[k], a);
                b  = fmaf(vl, c_hi[k], b);
                cc = fmaf(vh, c_lo[k], cc);
                d  = fmaf(vh, c_hi[k], d);
            }
            size_t oo = (size_t)img * o * o + (size_t)gr * o + gc;
            ll[oo] = a; lh[oo] = b; hl[oo] = cc; hh[oo] = d;
        }
    }
}

// ================= fused inverse level ======================================
// ll pitched (pitch llp, img stride llis), bands dense NxN (img stride bis).
// out: (B, On, On) dense, On = 2N-10.
#define OS  64          // output tile
#define JS  37          // band tile span = OS/2 + 5
#define JSP 38

__global__ __launch_bounds__(256) void idwt2(
    const float* __restrict__ ll, int llp, size_t llis,
    const float* __restrict__ lh, const float* __restrict__ hl,
    const float* __restrict__ hh, size_t bis,
    float* __restrict__ out, int On, int N, int tilesX)
{
    __shared__ float s_ll[JS * JSP], s_lh[JS * JSP];
    __shared__ float s_hl[JS * JSP], s_hh[JS * JSP];
    __shared__ float s_lo[OS * JSP], s_hi[OS * JSP];

    int img = blockIdx.y;
    int ty = blockIdx.x / tilesX, tx = blockIdx.x % tilesX;
    int r0 = ty * OS, c0 = tx * OS;
    int jr0 = r0 >> 1, jc0 = c0 >> 1;
    int tid = threadIdx.x;
    const float* pll = ll + (size_t)img * llis;
    const float* plh = lh + (size_t)img * bis;
    const float* phl = hl + (size_t)img * bis;
    const float* phh = hh + (size_t)img * bis;

    // stage A: load 4 band tiles (clamp — clamped rows only feed discarded outputs)
    for (int t = tid; t < JS * JS; t += 256) {
        int j = t % JS, i = t / JS;
        int jr = jr0 + i; if (jr > N - 1) jr = N - 1;
        int jc = jc0 + j; if (jc > N - 1) jc = N - 1;
        s_ll[i * JSP + j] = __ldg(pll + (size_t)jr * llp + jc);
        size_t bo = (size_t)jr * N + jc;
        s_lh[i * JSP + j] = __ldg(plh + bo);
        s_hl[i * JSP + j] = __ldg(phl + bo);
        s_hh[i * JSP + j] = __ldg(phh + bo);
    }
    __syncthreads();

    // stage B: height synthesis — row pair (2m, 2m+1) x JS cols
    for (int t = tid; t < (OS / 2) * JS; t += 256) {
        int j = t % JS, m = t / JS;
        float le = 0.f, lo_ = 0.f, he = 0.f, ho = 0.f;
#pragma unroll
        for (int k = 0; k < 6; ++k) {
            float a = s_ll[(m + k) * JSP + j], b = s_lh[(m + k) * JSP + j];
            float c = s_hl[(m + k) * JSP + j], d = s_hh[(m + k) * JSP + j];
            le  = fmaf(a, c_lo[10 - 2 * k], le);  le  = fmaf(b, c_hi[10 - 2 * k], le);
            lo_ = fmaf(a, c_lo[11 - 2 * k], lo_); lo_ = fmaf(b, c_hi[11 - 2 * k], lo_);
            he  = fmaf(c, c_lo[10 - 2 * k], he);  he  = fmaf(d, c_hi[10 - 2 * k], he);
            ho  = fmaf(c, c_lo[11 - 2 * k], ho);  ho  = fmaf(d, c_hi[11 - 2 * k], ho);
        }
        s_lo[(2 * m) * JSP + j] = le;  s_lo[(2 * m + 1) * JSP + j] = lo_;
        s_hi[(2 * m) * JSP + j] = he;  s_hi[(2 * m + 1) * JSP + j] = ho;
    }
    __syncthreads();

    // stage C: width synthesis — OS rows x col pair (2m, 2m+1), float2 store
    float* po = out + (size_t)img * On * On;
    for (int t = tid; t < OS * (OS / 2); t += 256) {
        int m = t % (OS / 2), r = t / (OS / 2);
        int gr = r0 + r, gc = c0 + 2 * m;
        if (gr < On && gc < On) {
            float se = 0.f, so = 0.f;
#pragma unroll
            for (int k = 0; k < 6; ++k) {
                float va = s_lo[r * JSP + m + k], vb = s_hi[r * JSP + m + k];
                se = fmaf(va, c_lo[10 - 2 * k], se); se = fmaf(vb, c_hi[10 - 2 * k], se);
                so = fmaf(va, c_lo[11 - 2 * k], so); so = fmaf(vb, c_hi[11 - 2 * k], so);
            }
            *reinterpret_cast<float2*>(po + (size_t)gr * On + gc) = make_float2(se, so);
        }
    }
}

// ================= channel mixing (smem input tiling) =======================
// yl: in (8b*32i, 1764), w (32i,32o,1764), out (8b*32o, 1764)
#define PT 128
__global__ __launch_bounds__(256) void mix_yl(
    const float* __restrict__ in, const float* __restrict__ w,
    float* __restrict__ out)
{
    const int P = 1764;
    __shared__ float s_in[32 * PT];
    int pt  = blockIdx.x % 14;
    int b   = blockIdx.x / 14;
    int p0  = pt * PT;
    int tid = threadIdx.x;
    for (int t = tid; t < 32 * PT; t += 256) {
        int p = t % PT, i = t / PT;
        s_in[t] = (p0 + p < P) ? __ldg(in + (size_t)(b * 32 + i) * P + p0 + p) : 0.f;
    }
    __syncthreads();
    for (int t = tid; t < 32 * PT; t += 256) {
        int p = t % PT, o = t / PT;
        if (p0 + p < P) {
            float s = 0.f;
#pragma unroll 8
            for (int i = 0; i < 32; ++i)
                s = fmaf(s_in[i * PT + p], __ldg(w + (size_t)(i * 32 + o) * P + p0 + p), s);
            out[(size_t)(b * 32 + o) * P + p0 + p] = s;
        }
    }
}

// yh: in (3c, 256, 1764), w (32i,32o,3c,1764), out (3c, 256, 1764)
__global__ __launch_bounds__(256) void mix_yh(
    const float* __restrict__ in, const float* __restrict__ w,
    float* __restrict__ out)
{
    const int P = 1764;
    __shared__ float s_in[32 * PT];
    int pt = blockIdx.x % 14;
    int b  = (blockIdx.x / 14) % 8;
    int c  = blockIdx.x / (14 * 8);
    int p0 = pt * PT;
    int tid = threadIdx.x;
    for (int t = tid; t < 32 * PT; t += 256) {
        int p = t % PT, i = t / PT;
        s_in[t] = (p0 + p < P)
            ? __ldg(in + (size_t)c * 256 * P + (size_t)(b * 32 + i) * P + p0 + p) : 0.f;
    }
    __syncthreads();
    for (int t = tid; t < 32 * PT; t += 256) {
        int p = t % PT, o = t / PT;
        if (p0 + p < P) {
            float s = 0.f;
#pragma unroll 8
            for (int i = 0; i < 32; ++i)
                s = fmaf(s_in[i * PT + p],
                         __ldg(w + ((size_t)(i * 32 + o) * 3 + c) * P + p0 + p), s);
            out[(size_t)c * 256 * P + (size_t)(b * 32 + o) * P + p0 + p] = s;
        }
    }
}

// ---------------------------------------------------------------------------
extern "C" void kernel_launch(void* const* d_in, const int* in_sizes, int n_in,
                              void* d_out, int out_size)
{
    (void)in_sizes; (void)n_in; (void)out_size;
    const float* x   = (const float*)d_in[0];
    const float* wyl = (const float*)d_in[1];
    const float* wyh = (const float*)d_in[2];
    float* out = (float*)d_out;

    float *ll1, *ll2, *ll3, *ll4, *mix, *h1, *h2, *h3, *h4;
    cudaGetSymbolAddress((void**)&ll1, g_ll1);
    cudaGetSymbolAddress((void**)&ll2, g_ll2);
    cudaGetSymbolAddress((void**)&ll3, g_ll3);
    cudaGetSymbolAddress((void**)&ll4, g_ll4);
    cudaGetSymbolAddress((void**)&mix, g_mix);
    cudaGetSymbolAddress((void**)&h1,  g_h1);
    cudaGetSymbolAddress((void**)&h2,  g_h2);
    cudaGetSymbolAddress((void**)&h3,  g_h3);
    cudaGetSymbolAddress((void**)&h4,  g_h4);

    const int B = 256;
    const size_t bs1 = 17438976;        // 256*261*261
    const size_t bs2 =  4734976;        // 256*136*136
    const size_t bs3 =  1364224;        // 256*73*73
    const size_t bs4 =   451584;        // 256*42*42

    // ---------------- forward DWT (one fused kernel per level) -------------
    fdwt2<<<dim3(9 * 9, B), 256>>>(x,   512, ll1, h1, h1 + bs1, h1 + 2 * bs1, 261, 9);
    fdwt2<<<dim3(5 * 5, B), 256>>>(ll1, 261, ll2, h2, h2 + bs2, h2 + 2 * bs2, 136, 5);
    fdwt2<<<dim3(3 * 3, B), 256>>>(ll2, 136, ll3, h3, h3 + bs3, h3 + 2 * bs3,  73, 3);
    fdwt2<<<dim3(2 * 2, B), 256>>>(ll3,  73, ll4, h4, h4 + bs4, h4 + 2 * bs4,  42, 2);

    // ---------------- channel mix ------------------------------------------
    mix_yl<<<8 * 14, 256>>>(ll4, wyl, mix);
    mix_yh<<<3 * 8 * 14, 256>>>(h4, wyh, mix + bs4);

    const float* myl = mix;
    const float* mh  = mix + bs4;

    // ---------------- inverse DWT (one fused kernel per level) -------------
    // L4: 42 -> 74  (ll74 into g_ll3, dense 74)
    idwt2<<<dim3(2 * 2, B), 256>>>(myl, 42, 1764,
                                   mh, mh + bs4, mh + 2 * bs4, 1764,
                                   ll3, 74, 42, 2);
    // L3: ll74 crop->73; 73 -> 136 (ll136 into g_ll2, dense 136)
    idwt2<<<dim3(3 * 3, B), 256>>>(ll3, 74, 5476,
                                   h3, h3 + bs3, h3 + 2 * bs3, 5329,
                                   ll2, 136, 73, 3);
    // L2: 136 -> 262 (ll262 into g_ll1, dense 262)
    idwt2<<<dim3(5 * 5, B), 256>>>(ll2, 136, 18496,
                                   h2, h2 + bs2, h2 + 2 * bs2, 18496,
                                   ll1, 262, 136, 5);
    // L1: ll262 crop->261; 261 -> 512 -> d_out
    idwt2<<<dim3(8 * 8, B), 256>>>(ll1, 262, 68644,
                                   h1, h1 + bs1, h1 + 2 * bs1, 68121,
                                   out, 512, 261, 8);
}

// round 8
// speedup vs baseline: 2.5869x; 1.1284x over previous
#include <cuda_runtime.h>

// ---------------------------------------------------------------------------
// WaveConv2d: 4-level db6 DWT -> per-pixel 32x32 channel mix at coarsest level
//             -> 4-level inverse DWT.  All fp32.
//
// R6: instruction-count surgery.
//   - structured thread maps (shifts/masks) instead of div/mod
//   - register sliding windows: multi-output per thread in all smem stages
//   - float2 LDS/LDG vector loads where alignment allows
// ---------------------------------------------------------------------------

#define DIV_UP(a,b) (((a)+(b)-1)/(b))

__device__ constexpr float c_lo[12] = {
   0.11154074335008017f,  0.4946238903983854f,   0.7511339080215775f,
   0.3152503517092432f,  -0.22626469396516913f, -0.12976686756709563f,
   0.09750160558707936f,  0.02752286553001629f, -0.031582039318031156f,
   0.0005538422009938016f,0.004777257511010651f,-0.00107730108499558f };

// RHI[t] = (-1)^t * H[11-t]
__device__ constexpr float c_hi[12] = {
  -0.00107730108499558f, -0.004777257511010651f, 0.0005538422009938016f,
   0.031582039318031156f, 0.02752286553001629f, -0.09750160558707936f,
  -0.12976686756709563f,  0.22626469396516913f,  0.3152503517092432f,
  -0.7511339080215775f,   0.4946238903983854f,  -0.11154074335008017f };

// ---------------- scratch (static device memory; reused across phases) -----
__device__ float g_ll1[17572864];  // fwd: ll1 (256*261*261) | inv: ll262 (256*262*262)
__device__ float g_ll2[ 4734976];  // fwd: ll2 (256*136*136) | inv: ll136
__device__ float g_ll3[ 1401856];  // fwd: ll3 (256*73*73)   | inv: ll74 (256*74*74)
__device__ float g_ll4[  451584];  // ll4 (256*42*42)
__device__ float g_mix[ 1806336];  // mixed yl + mixed yh4
__device__ float g_h1 [52316928];  // L1 bands lh,hl,hh (3*256*261*261)
__device__ float g_h2 [14204928];  // L2 bands
__device__ float g_h3 [ 4092672];  // L3 bands
__device__ float g_h4 [ 1354752];  // L4 bands

// ================= fused forward level ======================================
// in: (B, N, N) dense.  out: ll/lh/hl/hh, each (B, o, o) dense
#define OT  32          // output tile (both dims)
#define IT  74          // input tile span = 2*OT+10
#define ITP 76          // smem pitch (even -> 8B-aligned rows)
#define LHP 33

__global__ __launch_bounds__(256) void fdwt2(
    const float* __restrict__ in, int N,
    float* __restrict__ ll, float* __restrict__ lh,
    float* __restrict__ hl, float* __restrict__ hh,
    int o, int tilesX)
{
    __shared__ float s_in[IT * ITP];
    __shared__ float s_lo[IT * LHP];
    __shared__ float s_hi[IT * LHP];

    int img = blockIdx.y;
    int ty = blockIdx.x / tilesX, tx = blockIdx.x % tilesX;
    int r0 = ty * OT, c0 = tx * OT;
    int tid  = threadIdx.x;
    int lane = tid & 31, wid = tid >> 5;
    const float* ip = in + (size_t)img * N * N;
    int rbase = 2 * r0 - 10, cbase = 2 * c0 - 10;

    // ---- stage A: load 74x74 input tile ----
    bool interior = (rbase >= 0) && (rbase + IT <= N) && (cbase >= 0) && (cbase + IT <= N);
    if (interior && ((N & 1) == 0)) {
        // even N: every row start (rbase+i)*N + cbase is even -> float2 loads
        for (int i = wid; i < IT; i += 8) {
            const float2* src = reinterpret_cast<const float2*>(ip + (size_t)(rbase + i) * N + cbase);
            float2* dst = reinterpret_cast<float2*>(&s_in[i * ITP]);
            dst[lane] = __ldg(src + lane);
            if (lane < 5) dst[32 + lane] = __ldg(src + 32 + lane);
        }
    } else if (interior) {
        for (int i = wid; i < IT; i += 8) {
            const float* src = ip + (size_t)(rbase + i) * N + cbase;
            float* dst = &s_in[i * ITP];
            dst[lane]      = __ldg(src + lane);
            dst[lane + 32] = __ldg(src + lane + 32);
            if (lane < 10) dst[lane + 64] = __ldg(src + lane + 64);
        }
    } else {
        for (int t = tid; t < IT * IT; t += 256) {
            int j = t % IT, i = t / IT;
            int s = rbase + i; if (s < 0) s = -1 - s; if (s >= N) s = 2 * N - 1 - s;
            int u = cbase + j; if (u < 0) u = -1 - u; if (u >= N) u = 2 * N - 1 - u;
            s_in[i * ITP + j] = __ldg(ip + (size_t)s * N + u);
        }
    }
    __syncthreads();

    // ---- stage B: width analysis. thread -> (col group of 4, row stride 32) ----
    {
        int c4 = tid & 7;          // cols 4*c4 .. 4*c4+3
        int i0 = tid >> 3;         // rows i0, i0+32, i0+64
        for (int i = i0; i < IT; i += 32) {
            float w[18];
            const float2* p = reinterpret_cast<const float2*>(&s_in[i * ITP + 8 * c4]);
#pragma unroll
            for (int q = 0; q < 9; ++q) {
                float2 v = p[q];
                w[2 * q] = v.x; w[2 * q + 1] = v.y;
            }
#pragma unroll
            for (int k = 0; k < 4; ++k) {
                float sl = 0.f, sh = 0.f;
#pragma unroll
                for (int t = 0; t < 12; ++t) {
                    float v = w[2 * k + t];
                    sl = fmaf(v, c_lo[t], sl);
                    sh = fmaf(v, c_hi[t], sh);
                }
                s_lo[i * LHP + 4 * c4 + k] = sl;
                s_hi[i * LHP + 4 * c4 + k] = sh;
            }
        }
    }
    __syncthreads();

    // ---- stage C: height analysis. thread -> (col, 4-row group). 256 tasks, no loop ----
    {
        int c  = tid & 31;
        int rg = tid >> 5;         // rows 4*rg .. 4*rg+3, window rows 8*rg .. 8*rg+17
        float vl[18], vh[18];
#pragma unroll
        for (int k = 0; k < 18; ++k) {
            vl[k] = s_lo[(8 * rg + k) * LHP + c];
            vh[k] = s_hi[(8 * rg + k) * LHP + c];
        }
        int gc = c0 + c;
        if (gc < o) {
#pragma unroll
            for (int q = 0; q < 4; ++q) {
                int gr = r0 + 4 * rg + q;
                if (gr < o) {
                    float a = 0.f, b = 0.f, cc = 0.f, d = 0.f;
#pragma unroll
                    for (int k = 0; k < 12; ++k) {
                        float xl = vl[2 * q + k], xh = vh[2 * q + k];
                        a  = fmaf(xl, c_lo[k], a);
                        b  = fmaf(xl, c_hi[k], b);
                        cc = fmaf(xh, c_lo[k], cc);
                        d  = fmaf(xh, c_hi[k], d);
                    }
                    size_t oo = (size_t)img * o * o + (size_t)gr * o + gc;
                    ll[oo] = a; lh[oo] = b; hl[oo] = cc; hh[oo] = d;
                }
            }
        }
    }
}

// ================= fused inverse level ======================================
// ll pitched (pitch llp, img stride llis), bands dense NxN (img stride bis).
// out: (B, On, On) dense, On = 2N-10.
#define OS  64          // output tile
#define JS  37          // band tile span = OS/2 + 5
#define JSP 38

__global__ __launch_bounds__(256) void idwt2(
    const float* __restrict__ ll, int llp, size_t llis,
    const float* __restrict__ lh, const float* __restrict__ hl,
    const float* __restrict__ hh, size_t bis,
    float* __restrict__ out, int On, int N, int tilesX)
{
    __shared__ float s_ll[JS * JSP], s_lh[JS * JSP];
    __shared__ float s_hl[JS * JSP], s_hh[JS * JSP];
    __shared__ float s_lo[OS * JSP], s_hi[OS * JSP];

    int img = blockIdx.y;
    int ty = blockIdx.x / tilesX, tx = blockIdx.x % tilesX;
    int r0 = ty * OS, c0 = tx * OS;
    int jr0 = r0 >> 1, jc0 = c0 >> 1;
    int tid = threadIdx.x;
    const float* pll = ll + (size_t)img * llis;
    const float* plh = lh + (size_t)img * bis;
    const float* phl = hl + (size_t)img * bis;
    const float* phh = hh + (size_t)img * bis;

    // ---- stage A: load 4 band tiles (clamp feeds only discarded outputs) ----
    for (int t = tid; t < JS * JS; t += 256) {
        int j = t % JS, i = t / JS;
        int jr = jr0 + i; if (jr > N - 1) jr = N - 1;
        int jc = jc0 + j; if (jc > N - 1) jc = N - 1;
        s_ll[i * JSP + j] = __ldg(pll + (size_t)jr * llp + jc);
        size_t bo = (size_t)jr * N + jc;
        s_lh[i * JSP + j] = __ldg(plh + bo);
        s_hl[i * JSP + j] = __ldg(phl + bo);
        s_hh[i * JSP + j] = __ldg(phh + bo);
    }
    __syncthreads();

    // ---- stage B: height synthesis. thread -> (col, 4-output-row group) ----
    // group mg handles pairs m=2mg, 2mg+1 -> output rows 4mg..4mg+3,
    // consuming band rows 2mg..2mg+6 (7-row window).
    for (int t = tid; t < 16 * JS; t += 256) {
        int j  = t % JS;
        int mg = t / JS;
        float wa[7], wb[7], wc[7], wd[7];
#pragma unroll
        for (int k = 0; k < 7; ++k) {
            int rr = (2 * mg + k) * JSP + j;
            wa[k] = s_ll[rr]; wb[k] = s_lh[rr];
            wc[k] = s_hl[rr]; wd[k] = s_hh[rr];
        }
#pragma unroll
        for (int q = 0; q < 2; ++q) {        // pair m = 2mg + q, window offset q
            float le = 0.f, lo_ = 0.f, he = 0.f, ho = 0.f;
#pragma unroll
            for (int k = 0; k < 6; ++k) {
                float a = wa[q + k], b = wb[q + k];
                float c = wc[q + k], d = wd[q + k];
                le  = fmaf(a, c_lo[10 - 2 * k], le);  le  = fmaf(b, c_hi[10 - 2 * k], le);
                lo_ = fmaf(a, c_lo[11 - 2 * k], lo_); lo_ = fmaf(b, c_hi[11 - 2 * k], lo_);
                he  = fmaf(c, c_lo[10 - 2 * k], he);  he  = fmaf(d, c_hi[10 - 2 * k], he);
                ho  = fmaf(c, c_lo[11 - 2 * k], ho);  ho  = fmaf(d, c_hi[11 - 2 * k], ho);
            }
            int orow = 4 * mg + 2 * q;
            s_lo[orow * JSP + j] = le;  s_lo[(orow + 1) * JSP + j] = lo_;
            s_hi[orow * JSP + j] = he;  s_hi[(orow + 1) * JSP + j] = ho;
        }
    }
    __syncthreads();

    // ---- stage C: width synthesis. thread -> (4-col group, row stride 16) ----
    // group g covers output cols 4g..4g+3 (pairs m=2g, 2g+1), band cols 2g..2g+7.
    float* po = out + (size_t)img * On * On;
    {
        int g  = tid & 15;
        int rr0 = tid >> 4;
        for (int r = rr0; r < OS; r += 16) {
            float l[8], h[8];
            const float2* pl2 = reinterpret_cast<const float2*>(&s_lo[r * JSP + 2 * g]);
            const float2* ph2 = reinterpret_cast<const float2*>(&s_hi[r * JSP + 2 * g]);
#pragma unroll
            for (int q = 0; q < 4; ++q) {
                float2 a = pl2[q]; l[2 * q] = a.x; l[2 * q + 1] = a.y;
                float2 b = ph2[q]; h[2 * q] = b.x; h[2 * q + 1] = b.y;
            }
            int gr = r0 + r;
            if (gr < On) {
#pragma unroll
                for (int q = 0; q < 2; ++q) {    // pair m = 2g + q
                    int gc = c0 + 4 * g + 2 * q;
                    if (gc < On) {
                        float se = 0.f, so = 0.f;
#pragma unroll
                        for (int k = 0; k < 6; ++k) {
                            float va = l[q + k], vb = h[q + k];
                            se = fmaf(va, c_lo[10 - 2 * k], se); se = fmaf(vb, c_hi[10 - 2 * k], se);
                            so = fmaf(va, c_lo[11 - 2 * k], so); so = fmaf(vb, c_hi[11 - 2 * k], so);
                        }
                        *reinterpret_cast<float2*>(po + (size_t)gr * On + gc) = make_float2(se, so);
                    }
                }
            }
        }
    }
}

// ================= channel mixing (smem input tiling) =======================
#define PT 128
__global__ __launch_bounds__(256) void mix_yl(
    const float* __restrict__ in, const float* __restrict__ w,
    float* __restrict__ out)
{
    const int P = 1764;
    __shared__ float s_in[32 * PT];
    int pt  = blockIdx.x % 14;
    int b   = blockIdx.x / 14;
    int p0  = pt * PT;
    int tid = threadIdx.x;
    for (int t = tid; t < 32 * PT; t += 256) {
        int p = t % PT, i = t / PT;
        s_in[t] = (p0 + p < P) ? __ldg(in + (size_t)(b * 32 + i) * P + p0 + p) : 0.f;
    }
    __syncthreads();
    for (int t = tid; t < 32 * PT; t += 256) {
        int p = t % PT, o = t / PT;
        if (p0 + p < P) {
            float s = 0.f;
#pragma unroll 8
            for (int i = 0; i < 32; ++i)
                s = fmaf(s_in[i * PT + p], __ldg(w + (size_t)(i * 32 + o) * P + p0 + p), s);
            out[(size_t)(b * 32 + o) * P + p0 + p] = s;
        }
    }
}

__global__ __launch_bounds__(256) void mix_yh(
    const float* __restrict__ in, const float* __restrict__ w,
    float* __restrict__ out)
{
    const int P = 1764;
    __shared__ float s_in[32 * PT];
    int pt = blockIdx.x % 14;
    int b  = (blockIdx.x / 14) % 8;
    int c  = blockIdx.x / (14 * 8);
    int p0 = pt * PT;
    int tid = threadIdx.x;
    for (int t = tid; t < 32 * PT; t += 256) {
        int p = t % PT, i = t / PT;
        s_in[t] = (p0 + p < P)
            ? __ldg(in + (size_t)c * 256 * P + (size_t)(b * 32 + i) * P + p0 + p) : 0.f;
    }
    __syncthreads();
    for (int t = tid; t < 32 * PT; t += 256) {
        int p = t % PT, o = t / PT;
        if (p0 + p < P) {
            float s = 0.f;
#pragma unroll 8
            for (int i = 0; i < 32; ++i)
                s = fmaf(s_in[i * PT + p],
                         __ldg(w + ((size_t)(i * 32 + o) * 3 + c) * P + p0 + p), s);
            out[(size_t)c * 256 * P + (size_t)(b * 32 + o) * P + p0 + p] = s;
        }
    }
}

// ---------------------------------------------------------------------------
extern "C" void kernel_launch(void* const* d_in, const int* in_sizes, int n_in,
                              void* d_out, int out_size)
{
    (void)in_sizes; (void)n_in; (void)out_size;
    const float* x   = (const float*)d_in[0];
    const float* wyl = (const float*)d_in[1];
    const float* wyh = (const float*)d_in[2];
    float* out = (float*)d_out;

    float *ll1, *ll2, *ll3, *ll4, *mix, *h1, *h2, *h3, *h4;
    cudaGetSymbolAddress((void**)&ll1, g_ll1);
    cudaGetSymbolAddress((void**)&ll2, g_ll2);
    cudaGetSymbolAddress((void**)&ll3, g_ll3);
    cudaGetSymbolAddress((void**)&ll4, g_ll4);
    cudaGetSymbolAddress((void**)&mix, g_mix);
    cudaGetSymbolAddress((void**)&h1,  g_h1);
    cudaGetSymbolAddress((void**)&h2,  g_h2);
    cudaGetSymbolAddress((void**)&h3,  g_h3);
    cudaGetSymbolAddress((void**)&h4,  g_h4);

    const int B = 256;
    const size_t bs1 = 17438976;        // 256*261*261
    const size_t bs2 =  4734976;        // 256*136*136
    const size_t bs3 =  1364224;        // 256*73*73
    const size_t bs4 =   451584;        // 256*42*42

    // ---------------- forward DWT ------------------------------------------
    fdwt2<<<dim3(9 * 9, B), 256>>>(x,   512, ll1, h1, h1 + bs1, h1 + 2 * bs1, 261, 9);
    fdwt2<<<dim3(5 * 5, B), 256>>>(ll1, 261, ll2, h2, h2 + bs2, h2 + 2 * bs2, 136, 5);
    fdwt2<<<dim3(3 * 3, B), 256>>>(ll2, 136, ll3, h3, h3 + bs3, h3 + 2 * bs3,  73, 3);
    fdwt2<<<dim3(2 * 2, B), 256>>>(ll3,  73, ll4, h4, h4 + bs4, h4 + 2 * bs4,  42, 2);

    // ---------------- channel mix ------------------------------------------
    mix_yl<<<8 * 14, 256>>>(ll4, wyl, mix);
    mix_yh<<<3 * 8 * 14, 256>>>(h4, wyh, mix + bs4);

    const float* myl = mix;
    const float* mh  = mix + bs4;

    // ---------------- inverse DWT ------------------------------------------
    // L4: 42 -> 74  (ll74 into g_ll3, dense 74)
    idwt2<<<dim3(2 * 2, B), 256>>>(myl, 42, 1764,
                                   mh, mh + bs4, mh + 2 * bs4, 1764,
                                   ll3, 74, 42, 2);
    // L3: ll74 crop->73; 73 -> 136 (ll136 into g_ll2, dense 136)
    idwt2<<<dim3(3 * 3, B), 256>>>(ll3, 74, 5476,
                                   h3, h3 + bs3, h3 + 2 * bs3, 5329,
                                   ll2, 136, 73, 3);
    // L2: 136 -> 262 (ll262 into g_ll1, dense 262)
    idwt2<<<dim3(5 * 5, B), 256>>>(ll2, 136, 18496,
                                   h2, h2 + bs2, h2 + 2 * bs2, 18496,
                                   ll1, 262, 136, 5);
    // L1: ll262 crop->261; 261 -> 512 -> d_out
    idwt2<<<dim3(8 * 8, B), 256>>>(ll1, 262, 68644,
                                   h1, h1 + bs1, h1 + 2 * bs1, 68121,
                                   out, 512, 261, 8);
}

// round 9
// speedup vs baseline: 2.6427x; 1.0216x over previous
#include <cuda_runtime.h>

// ---------------------------------------------------------------------------
// WaveConv2d: 4-level db6 DWT -> per-pixel 32x32 channel mix at coarsest level
//             -> 4-level inverse DWT.  All fp32.
//
// R8: packed f32x2 FMA (SASS FFMA2) via inline PTX, with interleaved
//     (lo,hi) / (lh,hh) layouts so pairs come straight from LDS.64/LDG.64.
// ---------------------------------------------------------------------------

#define DIV_UP(a,b) (((a)+(b)-1)/(b))

__device__ constexpr float c_lo[12] = {
   0.11154074335008017f,  0.4946238903983854f,   0.7511339080215775f,
   0.3152503517092432f,  -0.22626469396516913f, -0.12976686756709563f,
   0.09750160558707936f,  0.02752286553001629f, -0.031582039318031156f,
   0.0005538422009938016f,0.004777257511010651f,-0.00107730108499558f };

// RHI[t] = (-1)^t * H[11-t]
__device__ constexpr float c_hi[12] = {
  -0.00107730108499558f, -0.004777257511010651f, 0.0005538422009938016f,
   0.031582039318031156f, 0.02752286553001629f, -0.09750160558707936f,
  -0.12976686756709563f,  0.22626469396516913f,  0.3152503517092432f,
  -0.7511339080215775f,   0.4946238903983854f,  -0.11154074335008017f };

// ---- packed f32x2 helpers (double = carrier for 2x f32 lanes) --------------
__device__ __forceinline__ double ffma2(double a, double b, double c) {
    double r;
    asm("fma.rn.f32x2 %0, %1, %2, %3;" : "=d"(r) : "d"(a), "d"(b), "d"(c));
    return r;
}
__device__ __forceinline__ double fpack(float x, float y) {   // lane0=x, lane1=y
    return __hiloint2double(__float_as_int(y), __float_as_int(x));
}
__device__ __forceinline__ float flo(double d) { return __int_as_float(__double2loint(d)); }
__device__ __forceinline__ float fhi(double d) { return __int_as_float(__double2hiint(d)); }
__device__ __forceinline__ double fdup(float x) { return fpack(x, x); }

// ---------------- scratch (static device memory) ----------------------------
__device__ float  g_ll1[17572864];   // fwd ll1 (256*261*261) | inv ll262 (256*262*262)
__device__ float  g_ll2[ 4734976];
__device__ float  g_ll3[ 1401856];   // fwd ll3 | inv ll74
__device__ float  g_ll4[  451584];
__device__ float  g_hl1[17438976];   // hl band planes (scalar)
__device__ float  g_hl2[ 4734976];
__device__ float  g_hl3[ 1364224];
__device__ float  g_hl4[  451584];
__device__ double g_bd1[17438976];   // (lh,hh) interleaved pair planes
__device__ double g_bd2[ 4734976];
__device__ double g_bd3[ 1364224];
__device__ double g_bd4[  451584];
__device__ float  g_mll4[ 451584];   // mixed ll4
__device__ float  g_mhl4[ 451584];   // mixed hl4
__device__ double g_mbd4[ 451584];   // mixed (lh,hh)

// ================= fused forward level ======================================
// in: (B,N,N) dense. out: ll,hl scalar planes + bd=(lh,hh) pair plane, (B,o,o)
#define OT   32
#define IT   74         // 2*OT+10
#define ITP  76         // s_in pitch (floats, even)
#define LHP2 33         // s_lh pitch (doubles)

__global__ __launch_bounds__(256) void fdwt2(
    const float* __restrict__ in, int N,
    float* __restrict__ ll, float* __restrict__ hl,
    double* __restrict__ bd, int o, int tilesX)
{
    __shared__ float  s_in[IT * ITP];
    __shared__ double s_lh[IT * LHP2];     // interleaved (lo,hi)

    int img = blockIdx.y;
    int ty = blockIdx.x / tilesX, tx = blockIdx.x % tilesX;
    int r0 = ty * OT, c0 = tx * OT;
    int tid  = threadIdx.x;
    int lane = tid & 31, wid = tid >> 5;
    const float* ip = in + (size_t)img * N * N;
    int rbase = 2 * r0 - 10, cbase = 2 * c0 - 10;

    // ---- stage A: load 74x74 input tile ----
    bool interior = (rbase >= 0) && (rbase + IT <= N) && (cbase >= 0) && (cbase + IT <= N);
    if (interior && ((N & 1) == 0)) {
        for (int i = wid; i < IT; i += 8) {
            const float2* src = reinterpret_cast<const float2*>(ip + (size_t)(rbase + i) * N + cbase);
            float2* dst = reinterpret_cast<float2*>(&s_in[i * ITP]);
            dst[lane] = __ldg(src + lane);
            if (lane < 5) dst[32 + lane] = __ldg(src + 32 + lane);
        }
    } else if (interior) {
        for (int i = wid; i < IT; i += 8) {
            const float* src = ip + (size_t)(rbase + i) * N + cbase;
            float* dst = &s_in[i * ITP];
            dst[lane]      = __ldg(src + lane);
            dst[lane + 32] = __ldg(src + lane + 32);
            if (lane < 10) dst[lane + 64] = __ldg(src + lane + 64);
        }
    } else {
        for (int t = tid; t < IT * IT; t += 256) {
            int j = t % IT, i = t / IT;
            int s = rbase + i; if (s < 0) s = -1 - s; if (s >= N) s = 2 * N - 1 - s;
            int u = cbase + j; if (u < 0) u = -1 - u; if (u >= N) u = 2 * N - 1 - u;
            s_in[i * ITP + j] = __ldg(ip + (size_t)s * N + u);
        }
    }
    __syncthreads();

    // ---- stage B: width analysis, packed (lo,hi) accumulators ----
    {
        double clh[12];
#pragma unroll
        for (int j = 0; j < 12; ++j) clh[j] = fpack(c_lo[j], c_hi[j]);

        int c4 = tid & 7;          // cols 4*c4 .. 4*c4+3
        int i0 = tid >> 3;         // rows i0, i0+32, i0+64
        for (int i = i0; i < IT; i += 32) {
            const double* p = reinterpret_cast<const double*>(&s_in[i * ITP + 8 * c4]);
            double dw[18];
#pragma unroll
            for (int q = 0; q < 9; ++q) {
                double v = p[q];
                dw[2 * q]     = fdup(flo(v));
                dw[2 * q + 1] = fdup(fhi(v));
            }
#pragma unroll
            for (int k = 0; k < 4; ++k) {
                double acc = 0.0;
#pragma unroll
                for (int t = 0; t < 12; ++t)
                    acc = ffma2(dw[2 * k + t], clh[t], acc);
                s_lh[i * LHP2 + 4 * c4 + k] = acc;
            }
        }
    }
    __syncthreads();

    // ---- stage C: height analysis, data pairs (vl,vh) x dup'd coeffs ----
    {
        double dlo[12], dhi[12];
#pragma unroll
        for (int j = 0; j < 12; ++j) { dlo[j] = fdup(c_lo[j]); dhi[j] = fdup(c_hi[j]); }

        int c  = tid & 31;
        int rg = tid >> 5;         // output rows 4*rg .. 4*rg+3
        double acc[8];             // per row q: accA=(ll,hl), accB=(lh,hh)
#pragma unroll
        for (int q = 0; q < 8; ++q) acc[q] = 0.0;
#pragma unroll
        for (int k = 0; k < 18; ++k) {
            double v = s_lh[(8 * rg + k) * LHP2 + c];
#pragma unroll
            for (int q = 0; q < 4; ++q) {
                int t = k - 2 * q;
                if (t >= 0 && t < 12) {
                    acc[2 * q]     = ffma2(v, dlo[t], acc[2 * q]);
                    acc[2 * q + 1] = ffma2(v, dhi[t], acc[2 * q + 1]);
                }
            }
        }
        int gc = c0 + c;
        if (gc < o) {
#pragma unroll
            for (int q = 0; q < 4; ++q) {
                int gr = r0 + 4 * rg + q;
                if (gr < o) {
                    size_t oo = (size_t)img * o * o + (size_t)gr * o + gc;
                    ll[oo] = flo(acc[2 * q]);
                    hl[oo] = fhi(acc[2 * q]);
                    bd[oo] = acc[2 * q + 1];          // (lh,hh) STG.64
                }
            }
        }
    }
}

// ================= fused inverse level ======================================
// ll pitched scalar; hl scalar plane; bd=(lh,hh) pair plane (dense NxN).
// out: (B,On,On) dense, On = 2N-10.
#define OS   64
#define JS   37         // band tile span = OS/2 + 5
#define JSP2 37         // smem pitch (doubles)

__global__ __launch_bounds__(256) void idwt2(
    const float* __restrict__ ll, int llp, size_t llis,
    const float* __restrict__ hl, const double* __restrict__ bd, size_t bis,
    float* __restrict__ out, int On, int N, int tilesX)
{
    __shared__ double s_ab[JS * JSP2];     // (ll, lh)
    __shared__ double s_cd[JS * JSP2];     // (hl, hh)
    __shared__ double s_lohi[OS * JSP2];   // (lo, hi) after height synth

    int img = blockIdx.y;
    int ty = blockIdx.x / tilesX, tx = blockIdx.x % tilesX;
    int r0 = ty * OS, c0 = tx * OS;
    int jr0 = r0 >> 1, jc0 = c0 >> 1;
    int tid = threadIdx.x;
    const float*  pll = ll + (size_t)img * llis;
    const float*  phl = hl + (size_t)img * bis;
    const double* pbd = bd + (size_t)img * bis;

    double clh[12];
#pragma unroll
    for (int j = 0; j < 12; ++j) clh[j] = fpack(c_lo[j], c_hi[j]);

    // ---- stage A: assemble (ll,lh) and (hl,hh) pair tiles ----
    for (int t = tid; t < JS * JS; t += 256) {
        int j = t % JS, i = t / JS;
        int jr = jr0 + i; if (jr > N - 1) jr = N - 1;
        int jc = jc0 + j; if (jc > N - 1) jc = N - 1;
        float  vll = __ldg(pll + (size_t)jr * llp + jc);
        size_t bo  = (size_t)jr * N + jc;
        float  vhl = __ldg(phl + bo);
        double vbd = __ldg(pbd + bo);      // (lh, hh)
        s_ab[i * JSP2 + j] = fpack(vll, flo(vbd));
        s_cd[i * JSP2 + j] = fpack(vhl, fhi(vbd));
    }
    __syncthreads();

    // ---- stage B: height synthesis (dot-trick), emit (lo,hi) pairs ----
    for (int t = tid; t < 16 * JS; t += 256) {
        int j  = t % JS;
        int mg = t / JS;
        double ab[7], cd[7];
#pragma unroll
        for (int k = 0; k < 7; ++k) {
            int rr = (2 * mg + k) * JSP2 + j;
            ab[k] = s_ab[rr]; cd[k] = s_cd[rr];
        }
#pragma unroll
        for (int q = 0; q < 2; ++q) {
            double aE = 0.0, aO = 0.0, cE = 0.0, cO = 0.0;
#pragma unroll
            for (int k = 0; k < 6; ++k) {
                aE = ffma2(ab[q + k], clh[10 - 2 * k], aE);
                aO = ffma2(ab[q + k], clh[11 - 2 * k], aO);
                cE = ffma2(cd[q + k], clh[10 - 2 * k], cE);
                cO = ffma2(cd[q + k], clh[11 - 2 * k], cO);
            }
            float le = flo(aE) + fhi(aE), he = flo(cE) + fhi(cE);
            float lo_ = flo(aO) + fhi(aO), ho = flo(cO) + fhi(cO);
            int orow = 4 * mg + 2 * q;
            s_lohi[orow * JSP2 + j]       = fpack(le,  he);
            s_lohi[(orow + 1) * JSP2 + j] = fpack(lo_, ho);
        }
    }
    __syncthreads();

    // ---- stage C: width synthesis (dot-trick), float2 stores ----
    float* po = out + (size_t)img * On * On;
    {
        int g   = tid & 15;        // output cols 4g..4g+3
        int rr0 = tid >> 4;
        for (int r = rr0; r < OS; r += 16) {
            double p[7];
#pragma unroll
            for (int k = 0; k < 7; ++k) p[k] = s_lohi[r * JSP2 + 2 * g + k];
            int gr = r0 + r;
            if (gr < On) {
#pragma unroll
                for (int q = 0; q < 2; ++q) {
                    int gc = c0 + 4 * g + 2 * q;
                    if (gc < On) {
                        double aE = 0.0, aO = 0.0;
#pragma unroll
                        for (int k = 0; k < 6; ++k) {
                            aE = ffma2(p[q + k], clh[10 - 2 * k], aE);
                            aO = ffma2(p[q + k], clh[11 - 2 * k], aO);
                        }
                        float se = flo(aE) + fhi(aE);
                        float so = flo(aO) + fhi(aO);
                        *reinterpret_cast<float2*>(po + (size_t)gr * On + gc) = make_float2(se, so);
                    }
                }
            }
        }
    }
}

// ================= channel mixing ===========================================
#define PT 128
// scalar mix: in (8b*32i, 1764) plane -> out (8b*32o, 1764); w stride ws, offset woff
__global__ __launch_bounds__(256) void mix_sc(
    const float* __restrict__ in, const float* __restrict__ w,
    float* __restrict__ out, int ws, int woff)
{
    const int P = 1764;
    __shared__ float s_in[32 * PT];
    int pt  = blockIdx.x % 14;
    int b   = blockIdx.x / 14;
    int p0  = pt * PT;
    int tid = threadIdx.x;
    for (int t = tid; t < 32 * PT; t += 256) {
        int p = t % PT, i = t / PT;
        s_in[t] = (p0 + p < P) ? __ldg(in + (size_t)(b * 32 + i) * P + p0 + p) : 0.f;
    }
    __syncthreads();
    for (int t = tid; t < 32 * PT; t += 256) {
        int p = t % PT, o = t / PT;
        if (p0 + p < P) {
            float s = 0.f;
#pragma unroll 8
            for (int i = 0; i < 32; ++i)
                s = fmaf(s_in[i * PT + p],
                         __ldg(w + ((size_t)(i * 32 + o) * ws + woff) * P + p0 + p), s);
            out[(size_t)(b * 32 + o) * P + p0 + p] = s;
        }
    }
}

// paired mix for (lh,hh): in/out are (lh,hh) pair planes; w channels 0 and 2
__global__ __launch_bounds__(256) void mix_bd(
    const double* __restrict__ in, const float* __restrict__ w,
    double* __restrict__ out)
{
    const int P = 1764;
    __shared__ double s_in[32 * PT];
    int pt  = blockIdx.x % 14;
    int b   = blockIdx.x / 14;
    int p0  = pt * PT;
    int tid = threadIdx.x;
    for (int t = tid; t < 32 * PT; t += 256) {
        int p = t % PT, i = t / PT;
        s_in[t] = (p0 + p < P) ? __ldg(in + (size_t)(b * 32 + i) * P + p0 + p) : 0.0;
    }
    __syncthreads();
    for (int t = tid; t < 32 * PT; t += 256) {
        int p = t % PT, o = t / PT;
        if (p0 + p < P) {
            double acc = 0.0;
#pragma unroll 8
            for (int i = 0; i < 32; ++i) {
                size_t wb = ((size_t)(i * 32 + o) * 3) * P + p0 + p;
                double wp = fpack(__ldg(w + wb), __ldg(w + wb + 2 * P));
                acc = ffma2(s_in[i * PT + p], wp, acc);
            }
            out[(size_t)(b * 32 + o) * P + p0 + p] = acc;
        }
    }
}

// ---------------------------------------------------------------------------
extern "C" void kernel_launch(void* const* d_in, const int* in_sizes, int n_in,
                              void* d_out, int out_size)
{
    (void)in_sizes; (void)n_in; (void)out_size;
    const float* x   = (const float*)d_in[0];
    const float* wyl = (const float*)d_in[1];
    const float* wyh = (const float*)d_in[2];
    float* out = (float*)d_out;

    float  *ll1, *ll2, *ll3, *ll4, *hl1, *hl2, *hl3, *hl4, *mll4, *mhl4;
    double *bd1, *bd2, *bd3, *bd4, *mbd4;
    cudaGetSymbolAddress((void**)&ll1, g_ll1);
    cudaGetSymbolAddress((void**)&ll2, g_ll2);
    cudaGetSymbolAddress((void**)&ll3, g_ll3);
    cudaGetSymbolAddress((void**)&ll4, g_ll4);
    cudaGetSymbolAddress((void**)&hl1, g_hl1);
    cudaGetSymbolAddress((void**)&hl2, g_hl2);
    cudaGetSymbolAddress((void**)&hl3, g_hl3);
    cudaGetSymbolAddress((void**)&hl4, g_hl4);
    cudaGetSymbolAddress((void**)&bd1, g_bd1);
    cudaGetSymbolAddress((void**)&bd2, g_bd2);
    cudaGetSymbolAddress((void**)&bd3, g_bd3);
    cudaGetSymbolAddress((void**)&bd4, g_bd4);
    cudaGetSymbolAddress((void**)&mll4, g_mll4);
    cudaGetSymbolAddress((void**)&mhl4, g_mhl4);
    cudaGetSymbolAddress((void**)&mbd4, g_mbd4);

    const int B = 256;

    // ---------------- forward DWT ------------------------------------------
    fdwt2<<<dim3(9 * 9, B), 256>>>(x,   512, ll1, hl1, bd1, 261, 9);
    fdwt2<<<dim3(5 * 5, B), 256>>>(ll1, 261, ll2, hl2, bd2, 136, 5);
    fdwt2<<<dim3(3 * 3, B), 256>>>(ll2, 136, ll3, hl3, bd3,  73, 3);
    fdwt2<<<dim3(2 * 2, B), 256>>>(ll3,  73, ll4, hl4, bd4,  42, 2);

    // ---------------- channel mix ------------------------------------------
    mix_sc<<<8 * 14, 256>>>(ll4, wyl, mll4, 1, 0);    // yl
    mix_sc<<<8 * 14, 256>>>(hl4, wyh, mhl4, 3, 1);    // hl band (c=1)
    mix_bd<<<8 * 14, 256>>>(bd4, wyh, mbd4);          // (lh,hh) bands (c=0,2)

    // ---------------- inverse DWT ------------------------------------------
    // L4: 42 -> 74  (ll74 into g_ll3, dense 74)
    idwt2<<<dim3(2 * 2, B), 256>>>(mll4, 42, 1764, mhl4, mbd4, 1764,
                                   ll3, 74, 42, 2);
    // L3: ll74 crop->73; 73 -> 136 (ll136 into g_ll2)
    idwt2<<<dim3(3 * 3, B), 256>>>(ll3, 74, 5476, hl3, bd3, 5329,
                                   ll2, 136, 73, 3);
    // L2: 136 -> 262 (ll262 into g_ll1)
    idwt2<<<dim3(5 * 5, B), 256>>>(ll2, 136, 18496, hl2, bd2, 18496,
                                   ll1, 262, 136, 5);
    // L1: ll262 crop->261; 261 -> 512 -> d_out
    idwt2<<<dim3(8 * 8, B), 256>>>(ll1, 262, 68644, hl1, bd1, 68121,
                                   out, 512, 261, 8);
}